// round 3
// baseline (speedup 1.0000x reference)
#include <cuda_runtime.h>
#include <cuda_bf16.h>
#include <math.h>

// Problem constants
#define BATCH 64
#define TSTEPS 512
#define DDIM 128
#define HDIM 1024

// ---------------------------------------------------------------------------
// Kernel A: xp = x @ Wx + b  written directly into out[B,T,H]
//   M = B*T = 32768, K = 128, N = 1024
//   BM=64, BN=64, BK=32, 256 threads, 4x4 register tile per thread
// ---------------------------------------------------------------------------
__global__ __launch_bounds__(256) void xp_kernel(
    const float* __restrict__ x,
    const float* __restrict__ Wx,
    const float* __restrict__ bias,
    float* __restrict__ out)
{
    __shared__ float xs[64][33];      // +1 pad: conflict-free column reads
    __shared__ float ws[32][68];      // pad to 68 (272B row, 16B aligned)

    const int bx = blockIdx.x;        // N tile: 0..15
    const int by = blockIdx.y;        // M tile: 0..511
    const int tid = threadIdx.x;
    const int tx = tid & 15;          // 0..15
    const int ty = tid >> 4;          // 0..15
    const int row0 = by * 64;
    const int col0 = bx * 64;

    float acc[4][4];
#pragma unroll
    for (int i = 0; i < 4; i++)
#pragma unroll
        for (int j = 0; j < 4; j++) acc[i][j] = 0.0f;

    for (int k0 = 0; k0 < DDIM; k0 += 32) {
        // load x tile: 64 x 32 floats = 512 float4
        for (int i = tid; i < 512; i += 256) {
            int m = i >> 3;
            int c = (i & 7) << 2;
            float4 v = *(const float4*)&x[(size_t)(row0 + m) * DDIM + k0 + c];
            xs[m][c + 0] = v.x; xs[m][c + 1] = v.y;
            xs[m][c + 2] = v.z; xs[m][c + 3] = v.w;
        }
        // load Wx tile: 32 x 64 floats = 512 float4
        for (int i = tid; i < 512; i += 256) {
            int k = i >> 4;
            int c = (i & 15) << 2;
            *(float4*)&ws[k][c] =
                *(const float4*)&Wx[(size_t)(k0 + k) * HDIM + col0 + c];
        }
        __syncthreads();

#pragma unroll
        for (int kk = 0; kk < 32; kk++) {
            float a[4], bv[4];
#pragma unroll
            for (int i = 0; i < 4; i++) a[i] = xs[ty * 4 + i][kk];
#pragma unroll
            for (int j = 0; j < 4; j++) bv[j] = ws[kk][tx * 4 + j];
#pragma unroll
            for (int i = 0; i < 4; i++)
#pragma unroll
                for (int j = 0; j < 4; j++)
                    acc[i][j] = fmaf(a[i], bv[j], acc[i][j]);
        }
        __syncthreads();
    }

#pragma unroll
    for (int i = 0; i < 4; i++) {
        int row = row0 + ty * 4 + i;
#pragma unroll
        for (int j = 0; j < 4; j++) {
            int col = col0 + tx * 4 + j;
            out[(size_t)row * HDIM + col] = acc[i][j] + bias[col];
        }
    }
}

// ---------------------------------------------------------------------------
// Kernel B: one recurrence step, in place on out.
//   out[:,t,:] = tanh(out[:,t,:] + out[:,t-1,:] @ Wh)   (h := 0 for t==0)
//   grid = 128 blocks (Ntile = 8 columns each), 256 threads.
//   Each thread owns 2 outputs: rows (m2, m2+32), one column n.
// ---------------------------------------------------------------------------
__global__ __launch_bounds__(256) void rnn_step_kernel(
    float* __restrict__ out,
    const float* __restrict__ Wh,
    int t)
{
    const int n0 = blockIdx.x * 8;            // column tile base
    const int tid = threadIdx.x;
    const int n  = tid & 7;                   // 0..7
    const int m2 = tid >> 3;                  // 0..31

    float acc0 = 0.0f, acc1 = 0.0f;

    __shared__ float hs[64][132];             // padded: 132 % 32 == 4
    __shared__ float ws[8][132];              // Wh tile transposed [n][k]

    if (t > 0) {
        const size_t hbase = (size_t)(t - 1) * HDIM;  // + m*T*H
        for (int k0 = 0; k0 < HDIM; k0 += 128) {
            // load h tile: 64 rows x 128 k = 2048 float4
            for (int i = tid; i < 2048; i += 256) {
                int m = i >> 5;
                int c = (i & 31) << 2;
                *(float4*)&hs[m][c] = *(const float4*)
                    &out[(size_t)m * TSTEPS * HDIM + hbase + k0 + c];
            }
            // load Wh tile transposed: 128 k x 8 n
            for (int i = tid; i < 1024; i += 256) {
                int k = i >> 3;
                int nn = i & 7;
                ws[nn][k] = Wh[(size_t)(k0 + k) * HDIM + n0 + nn];
            }
            __syncthreads();

#pragma unroll
            for (int kk = 0; kk < 128; kk += 4) {
                float4 w = *(float4*)&ws[n][kk];
                float4 a = *(float4*)&hs[m2][kk];
                float4 b = *(float4*)&hs[m2 + 32][kk];
                acc0 = fmaf(a.x, w.x, acc0);
                acc0 = fmaf(a.y, w.y, acc0);
                acc0 = fmaf(a.z, w.z, acc0);
                acc0 = fmaf(a.w, w.w, acc0);
                acc1 = fmaf(b.x, w.x, acc1);
                acc1 = fmaf(b.y, w.y, acc1);
                acc1 = fmaf(b.z, w.z, acc1);
                acc1 = fmaf(b.w, w.w, acc1);
            }
            __syncthreads();
        }
    }

    const size_t o0 = (size_t)m2 * TSTEPS * HDIM + (size_t)t * HDIM + n0 + n;
    const size_t o1 = (size_t)(m2 + 32) * TSTEPS * HDIM + (size_t)t * HDIM + n0 + n;
    out[o0] = tanhf(out[o0] + acc0);
    out[o1] = tanhf(out[o1] + acc1);
}

// ---------------------------------------------------------------------------
// kernel_launch
//   inputs (metadata order): x [B,T,D], Wx [D,H], Wh [H,H], b [H]
//   output: [B,T,H] float32
// ---------------------------------------------------------------------------
extern "C" void kernel_launch(void* const* d_in, const int* in_sizes, int n_in,
                              void* d_out, int out_size)
{
    (void)in_sizes; (void)n_in; (void)out_size;
    const float* x    = (const float*)d_in[0];
    const float* Wx   = (const float*)d_in[1];
    const float* Wh   = (const float*)d_in[2];
    const float* bias = (const float*)d_in[3];
    float* out = (float*)d_out;

    // 1) xp = x @ Wx + b  -> out
    dim3 gridA(HDIM / 64, (BATCH * TSTEPS) / 64);
    xp_kernel<<<gridA, 256>>>(x, Wx, bias, out);

    // 2) sequential recurrence, in place
    for (int t = 0; t < TSTEPS; t++) {
        rnn_step_kernel<<<128, 256>>>(out, Wh, t);
    }
}

// round 8
// speedup vs baseline: 3.3020x; 3.3020x over previous
#include <cuda_runtime.h>
#include <math.h>

// Problem constants
#define BATCH 64
#define TSTEPS 512
#define DDIM 128
#define HDIM 1024
#define GRID 128          // 16 n-tiles x 8 k-splits; must be <= #SMs (148)
#define KCHUNK 128
#define NTILE 64

// Double-buffered split-K partials: 2*8*64*1024*4B = 4 MB (static, loaded with module)
__device__ float g_partial[2][8][BATCH][HDIM];
// Monotonic barrier ticket counter (never reset; wrap-safe compare)
__device__ unsigned g_count;

// ---------------------------------------------------------------------------
// Kernel A: xp = x @ Wx + b  -> out[B,T,H]   (M=32768, K=128, N=1024)
// ---------------------------------------------------------------------------
__global__ __launch_bounds__(256) void xp_kernel(
    const float* __restrict__ x,
    const float* __restrict__ Wx,
    const float* __restrict__ bias,
    float* __restrict__ out)
{
    __shared__ float xs[64][33];
    __shared__ float ws[32][68];

    const int bx = blockIdx.x;
    const int by = blockIdx.y;
    const int tid = threadIdx.x;
    const int tx = tid & 15;
    const int ty = tid >> 4;
    const int row0 = by * 64;
    const int col0 = bx * 64;

    float acc[4][4];
#pragma unroll
    for (int i = 0; i < 4; i++)
#pragma unroll
        for (int j = 0; j < 4; j++) acc[i][j] = 0.0f;

    for (int k0 = 0; k0 < DDIM; k0 += 32) {
        for (int i = tid; i < 512; i += 256) {
            int m = i >> 3;
            int c = (i & 7) << 2;
            float4 v = *(const float4*)&x[(size_t)(row0 + m) * DDIM + k0 + c];
            xs[m][c + 0] = v.x; xs[m][c + 1] = v.y;
            xs[m][c + 2] = v.z; xs[m][c + 3] = v.w;
        }
        for (int i = tid; i < 512; i += 256) {
            int k = i >> 4;
            int c = (i & 15) << 2;
            *(float4*)&ws[k][c] =
                *(const float4*)&Wx[(size_t)(k0 + k) * HDIM + col0 + c];
        }
        __syncthreads();

#pragma unroll
        for (int kk = 0; kk < 32; kk++) {
            float a[4], bv[4];
#pragma unroll
            for (int i = 0; i < 4; i++) a[i] = xs[ty * 4 + i][kk];
#pragma unroll
            for (int j = 0; j < 4; j++) bv[j] = ws[kk][tx * 4 + j];
#pragma unroll
            for (int i = 0; i < 4; i++)
#pragma unroll
                for (int j = 0; j < 4; j++)
                    acc[i][j] = fmaf(a[i], bv[j], acc[i][j]);
        }
        __syncthreads();
    }

#pragma unroll
    for (int i = 0; i < 4; i++) {
        int row = row0 + ty * 4 + i;
#pragma unroll
        for (int j = 0; j < 4; j++) {
            int col = col0 + tx * 4 + j;
            out[(size_t)row * HDIM + col] = acc[i][j] + bias[col];
        }
    }
}

// ---------------------------------------------------------------------------
// Kernel B: persistent recurrence. 128 blocks = (16 n-tiles) x (8 k-splits).
// Block (nb, ks):
//   phase t: [writer nb==0: flush h_{t-1} k-chunk from smem to out]
//            reduce  h_t[:, kchunk] = tanh(xp_t + sum_s partial[rp][s])
//            GEMM    partial[wp][ks][:, ntile] = h_t_chunk @ Wh[kchunk, ntile]
//            grid barrier
// Wh tile lives in smem for the whole kernel. Each warp owns 8 h-rows
// (reduce producer == GEMM consumer), so only __syncwarp between them.
// ---------------------------------------------------------------------------
struct SmemLayout {
    float hs[64][132];    // h_t chunk [m][k], padded
    float ws[128][68];    // Wh[kchunk][ntile], padded, persistent
};

__global__ void __launch_bounds__(256, 1) rnn_persistent(
    float* __restrict__ out,
    const float* __restrict__ Wh)
{
    extern __shared__ char smem_raw[];
    SmemLayout* sm = reinterpret_cast<SmemLayout*>(smem_raw);

    const int bx = blockIdx.x;
    const int ks = bx >> 4;          // 0..7  k-split
    const int nb = bx & 15;          // 0..15 n-tile
    const int k0 = ks * KCHUNK;
    const int n0 = nb * NTILE;
    const int tid = threadIdx.x;
    const int tx = tid & 15;
    const int ty = tid >> 4;         // 0..15 -> rows ty*4..ty*4+3
    const int w  = tid >> 5;         // warp 0..7
    const int ln = tid & 31;

    // Preload this block's Wh tile once (reused for all 512 steps)
    for (int i = tid; i < 2048; i += 256) {
        int k = i >> 4;
        int c = (i & 15) << 2;
        *(float4*)&sm->ws[k][c] =
            *(const float4*)&Wh[(size_t)(k0 + k) * HDIM + n0 + c];
    }
    __syncthreads();

    // Reduce mapping: warp w owns rows w*8 .. w*8+7 (same rows its GEMM reads)
    const int rrow  = w * 8 + (ln >> 2);     // m row
    const int cbase = (ln & 3) << 2;         // k float-offset base

    for (int t = 0; t < TSTEPS; t++) {
        // ---- flush h_{t-1} (still in smem) to out; safe: xp_{t-1} consumed ----
        if (t > 0) {
            if (nb == 0) {
                for (int i = tid; i < 2048; i += 256) {
                    int m = i >> 5;
                    int c = (i & 31) << 2;
                    *(float4*)&out[(size_t)m * TSTEPS * HDIM
                                   + (size_t)(t - 1) * HDIM + k0 + c] =
                        *(const float4*)&sm->hs[m][c];
                }
            }
            __syncthreads();   // hs stable before overwrite (uniform branch)
        }

        // ---- reduce own 8 rows: h_t[rrow][k0..k0+127] ----
        {
            const float* xp_row = out + (size_t)rrow * TSTEPS * HDIM
                                  + (size_t)t * HDIM + k0;
            const int rp = (t - 1) & 1;
#pragma unroll
            for (int g = 0; g < 8; g++) {
                const int kc = cbase + (g << 4);      // 0..124
                float4 s = *(const float4*)(xp_row + kc);
                if (t > 0) {
#pragma unroll
                    for (int sp = 0; sp < 8; sp++) {
                        float4 p = __ldcg((const float4*)
                            &g_partial[rp][sp][rrow][k0 + kc]);
                        s.x += p.x; s.y += p.y; s.z += p.z; s.w += p.w;
                    }
                }
                s.x = tanhf(s.x); s.y = tanhf(s.y);
                s.z = tanhf(s.z); s.w = tanhf(s.w);
                *(float4*)&sm->hs[rrow][kc] = s;
            }
        }
        __syncwarp();   // warp's own rows complete; GEMM reads only those

        if (t < TSTEPS - 1) {
            // ---- GEMM: partial[wp][ks][:, n0:n0+64] += hs @ ws ----
            float acc[4][4];
#pragma unroll
            for (int i = 0; i < 4; i++)
#pragma unroll
                for (int j = 0; j < 4; j++) acc[i][j] = 0.0f;

            const int r0 = ty * 4;
#pragma unroll 2
            for (int kk = 0; kk < KCHUNK; kk += 4) {
                float4 a0 = *(const float4*)&sm->hs[r0 + 0][kk];
                float4 a1 = *(const float4*)&sm->hs[r0 + 1][kk];
                float4 a2 = *(const float4*)&sm->hs[r0 + 2][kk];
                float4 a3 = *(const float4*)&sm->hs[r0 + 3][kk];
#pragma unroll
                for (int q = 0; q < 4; q++) {
                    float4 b4 = *(const float4*)&sm->ws[kk + q][tx * 4];
                    const float av0 = ((const float*)&a0)[q];
                    const float av1 = ((const float*)&a1)[q];
                    const float av2 = ((const float*)&a2)[q];
                    const float av3 = ((const float*)&a3)[q];
                    acc[0][0] = fmaf(av0, b4.x, acc[0][0]);
                    acc[0][1] = fmaf(av0, b4.y, acc[0][1]);
                    acc[0][2] = fmaf(av0, b4.z, acc[0][2]);
                    acc[0][3] = fmaf(av0, b4.w, acc[0][3]);
                    acc[1][0] = fmaf(av1, b4.x, acc[1][0]);
                    acc[1][1] = fmaf(av1, b4.y, acc[1][1]);
                    acc[1][2] = fmaf(av1, b4.z, acc[1][2]);
                    acc[1][3] = fmaf(av1, b4.w, acc[1][3]);
                    acc[2][0] = fmaf(av2, b4.x, acc[2][0]);
                    acc[2][1] = fmaf(av2, b4.y, acc[2][1]);
                    acc[2][2] = fmaf(av2, b4.z, acc[2][2]);
                    acc[2][3] = fmaf(av2, b4.w, acc[2][3]);
                    acc[3][0] = fmaf(av3, b4.x, acc[3][0]);
                    acc[3][1] = fmaf(av3, b4.y, acc[3][1]);
                    acc[3][2] = fmaf(av3, b4.z, acc[3][2]);
                    acc[3][3] = fmaf(av3, b4.w, acc[3][3]);
                }
            }

            const int wp = t & 1;
#pragma unroll
            for (int i = 0; i < 4; i++) {
                *(float4*)&g_partial[wp][ks][r0 + i][n0 + tx * 4] =
                    make_float4(acc[i][0], acc[i][1], acc[i][2], acc[i][3]);
            }

            // ---- grid barrier (monotonic ticket; wrap-safe; replay-safe) ----
            __threadfence();
            __syncthreads();
            if (tid == 0) {
                unsigned tk = atomicAdd(&g_count, 1u);
                unsigned target = ((tk >> 7) + 1u) << 7;   // gridDim = 128
                while ((int)(*(volatile unsigned*)&g_count) - (int)target < 0) { }
                __threadfence();
            }
            __syncthreads();
        }
    }

    // ---- final flush: h_{511} ----
    __syncthreads();
    if (nb == 0) {
        for (int i = tid; i < 2048; i += 256) {
            int m = i >> 5;
            int c = (i & 31) << 2;
            *(float4*)&out[(size_t)m * TSTEPS * HDIM
                           + (size_t)(TSTEPS - 1) * HDIM + k0 + c] =
                *(const float4*)&sm->hs[m][c];
        }
    }
}

// ---------------------------------------------------------------------------
// kernel_launch: 2 graph nodes total.
// ---------------------------------------------------------------------------
extern "C" void kernel_launch(void* const* d_in, const int* in_sizes, int n_in,
                              void* d_out, int out_size)
{
    (void)in_sizes; (void)n_in; (void)out_size;
    const float* x    = (const float*)d_in[0];
    const float* Wx   = (const float*)d_in[1];
    const float* Wh   = (const float*)d_in[2];
    const float* bias = (const float*)d_in[3];
    float* out = (float*)d_out;

    // 1) xp = x @ Wx + b  -> out
    dim3 gridA(HDIM / 64, (BATCH * TSTEPS) / 64);
    xp_kernel<<<gridA, 256>>>(x, Wx, bias, out);

    // 2) persistent recurrence (single launch, internal grid barriers)
    cudaFuncSetAttribute(rnn_persistent,
                         cudaFuncAttributeMaxDynamicSharedMemorySize,
                         (int)sizeof(SmemLayout));
    rnn_persistent<<<GRID, 256, sizeof(SmemLayout)>>>(out, Wh);
}

// round 13
// speedup vs baseline: 3.6777x; 1.1138x over previous
#include <cuda_runtime.h>
#include <math.h>

// Problem constants
#define BATCH 64
#define TSTEPS 512
#define DDIM 128
#define HDIM 1024
#define GRID 128          // 16 n-tiles x 8 k-splits
#define KCHUNK 128
#define NTILE 64

// Double-buffered split-K partials: 2*8*64*1024*4B = 4 MB (static)
__device__ float g_partial[2][8][BATCH][HDIM];
// Monotonic barrier tickets (never reset; wrap-safe compares)
__device__ unsigned g_count;        // full grid barrier (128 arrivals/phase)
__device__ unsigned g_gcount[8];    // per-ks-group barriers (16 arrivals/phase)

// ---------------------------------------------------------------------------
// Kernel A: xp = x @ Wx + b  -> out[B,T,H]   (M=32768, K=128, N=1024)
// ---------------------------------------------------------------------------
__global__ __launch_bounds__(256) void xp_kernel(
    const float* __restrict__ x,
    const float* __restrict__ Wx,
    const float* __restrict__ bias,
    float* __restrict__ out)
{
    __shared__ float xs[64][33];
    __shared__ float ws[32][68];

    const int bx = blockIdx.x;
    const int by = blockIdx.y;
    const int tid = threadIdx.x;
    const int tx = tid & 15;
    const int ty = tid >> 4;
    const int row0 = by * 64;
    const int col0 = bx * 64;

    float acc[4][4];
#pragma unroll
    for (int i = 0; i < 4; i++)
#pragma unroll
        for (int j = 0; j < 4; j++) acc[i][j] = 0.0f;

    for (int k0 = 0; k0 < DDIM; k0 += 32) {
        for (int i = tid; i < 512; i += 256) {
            int m = i >> 3;
            int c = (i & 7) << 2;
            float4 v = *(const float4*)&x[(size_t)(row0 + m) * DDIM + k0 + c];
            xs[m][c + 0] = v.x; xs[m][c + 1] = v.y;
            xs[m][c + 2] = v.z; xs[m][c + 3] = v.w;
        }
        for (int i = tid; i < 512; i += 256) {
            int k = i >> 4;
            int c = (i & 15) << 2;
            *(float4*)&ws[k][c] =
                *(const float4*)&Wx[(size_t)(k0 + k) * HDIM + col0 + c];
        }
        __syncthreads();

#pragma unroll
        for (int kk = 0; kk < 32; kk++) {
            float a[4], bv[4];
#pragma unroll
            for (int i = 0; i < 4; i++) a[i] = xs[ty * 4 + i][kk];
#pragma unroll
            for (int j = 0; j < 4; j++) bv[j] = ws[kk][tx * 4 + j];
#pragma unroll
            for (int i = 0; i < 4; i++)
#pragma unroll
                for (int j = 0; j < 4; j++)
                    acc[i][j] = fmaf(a[i], bv[j], acc[i][j]);
        }
        __syncthreads();
    }

#pragma unroll
    for (int i = 0; i < 4; i++) {
        int row = row0 + ty * 4 + i;
#pragma unroll
        for (int j = 0; j < 4; j++) {
            int col = col0 + tx * 4 + j;
            out[(size_t)row * HDIM + col] = acc[i][j] + bias[col];
        }
    }
}

// ---------------------------------------------------------------------------
// Kernel B: persistent recurrence. 128 blocks = (16 n-tiles nb) x (8 k-splits ks).
// Phase t for block (nb, ks):
//   owner-reduce: rows nb*4..nb*4+3 of k-chunk ks:
//       h = tanh(xp + sum_sp partial[rp][sp]); write h in place into out[:,t,:]
//   group barrier over the 16 blocks sharing ks (h of this k-chunk published)
//   per-warp: load own 8 GEMM rows of h from out -> smem, __syncwarp
//   GEMM: partial[wp][ks][:, n-tile nb] = hs @ Wh_tile   (Wh tile smem-resident)
//   full grid barrier
// ---------------------------------------------------------------------------
struct SmemLayout {
    float hs[64][132];    // h_t chunk [m][k], padded
    float ws[128][68];    // Wh[kchunk][ntile], padded, persistent
};

__global__ void __launch_bounds__(256, 1) rnn_persistent(
    float* __restrict__ out,
    const float* __restrict__ Wh)
{
    extern __shared__ char smem_raw[];
    SmemLayout* sm = reinterpret_cast<SmemLayout*>(smem_raw);

    const int bx = blockIdx.x;
    const int ks = bx >> 4;          // 0..7  k-split
    const int nb = bx & 15;          // 0..15 n-tile
    const int k0 = ks * KCHUNK;
    const int n0 = nb * NTILE;
    const int tid = threadIdx.x;
    const int tx = tid & 15;
    const int ty = tid >> 4;         // 0..15 -> GEMM rows ty*4..ty*4+3
    const int w  = tid >> 5;         // warp 0..7 -> owns hs rows w*8..w*8+7
    const int ln = tid & 31;

    // Preload this block's Wh tile once (reused for all 512 steps)
    for (int i = tid; i < 2048; i += 256) {
        int k = i >> 4;
        int c = (i & 15) << 2;
        *(float4*)&sm->ws[k][c] =
            *(const float4*)&Wh[(size_t)(k0 + k) * HDIM + n0 + c];
    }
    __syncthreads();

    // Owner-reduce mapping (threads 0..127): row nb*4 + (tid>>5), col4 = tid&31
    const int orow = nb * 4 + (tid >> 5);
    const int oc   = (tid & 31) << 2;

    for (int t = 0; t < TSTEPS; t++) {
        // ---- owner-reduce: 4 rows of this k-chunk, written in place ----
        if (tid < 128) {
            float* xp_ptr = out + (size_t)orow * TSTEPS * HDIM
                            + (size_t)t * HDIM + k0 + oc;
            float4 s = *(const float4*)xp_ptr;
            if (t > 0) {
                const int rp = (t - 1) & 1;
#pragma unroll
                for (int sp = 0; sp < 8; sp++) {
                    float4 p = __ldcg((const float4*)
                        &g_partial[rp][sp][orow][k0 + oc]);
                    s.x += p.x; s.y += p.y; s.z += p.z; s.w += p.w;
                }
            }
            s.x = tanhf(s.x); s.y = tanhf(s.y);
            s.z = tanhf(s.z); s.w = tanhf(s.w);
            *(float4*)xp_ptr = s;     // out[:,t,:] now holds h_t (this slice)
        }

        if (t < TSTEPS - 1) {
            // ---- group barrier: 16 blocks sharing this ks ----
            __threadfence();
            __syncthreads();
            if (tid == 0) {
                unsigned tk = atomicAdd(&g_gcount[ks], 1u);
                unsigned target = ((tk >> 4) + 1u) << 4;     // 16 arrivals
                while ((int)(*(volatile unsigned*)&g_gcount[ks])
                       - (int)target < 0) { }
                __threadfence();
            }
            __syncthreads();

            // ---- per-warp: load own 8 h rows from out into smem ----
            {
                const size_t hb = (size_t)t * HDIM + k0;
#pragma unroll
                for (int j = ln; j < 256; j += 32) {
                    int m = (w << 3) + (j >> 5);
                    int c = (j & 31) << 2;
                    *(float4*)&sm->hs[m][c] = __ldcg((const float4*)
                        &out[(size_t)m * TSTEPS * HDIM + hb + c]);
                }
            }
            __syncwarp();   // warp reads only the rows it just wrote

            // ---- GEMM: partial[wp][ks][:, n0:n0+64] = hs @ ws ----
            float acc[4][4];
#pragma unroll
            for (int i = 0; i < 4; i++)
#pragma unroll
                for (int j = 0; j < 4; j++) acc[i][j] = 0.0f;

            const int r0 = ty * 4;
#pragma unroll 2
            for (int kk = 0; kk < KCHUNK; kk += 4) {
                float4 a0 = *(const float4*)&sm->hs[r0 + 0][kk];
                float4 a1 = *(const float4*)&sm->hs[r0 + 1][kk];
                float4 a2 = *(const float4*)&sm->hs[r0 + 2][kk];
                float4 a3 = *(const float4*)&sm->hs[r0 + 3][kk];
#pragma unroll
                for (int q = 0; q < 4; q++) {
                    float4 b4 = *(const float4*)&sm->ws[kk + q][tx * 4];
                    const float av0 = ((const float*)&a0)[q];
                    const float av1 = ((const float*)&a1)[q];
                    const float av2 = ((const float*)&a2)[q];
                    const float av3 = ((const float*)&a3)[q];
                    acc[0][0] = fmaf(av0, b4.x, acc[0][0]);
                    acc[0][1] = fmaf(av0, b4.y, acc[0][1]);
                    acc[0][2] = fmaf(av0, b4.z, acc[0][2]);
                    acc[0][3] = fmaf(av0, b4.w, acc[0][3]);
                    acc[1][0] = fmaf(av1, b4.x, acc[1][0]);
                    acc[1][1] = fmaf(av1, b4.y, acc[1][1]);
                    acc[1][2] = fmaf(av1, b4.z, acc[1][2]);
                    acc[1][3] = fmaf(av1, b4.w, acc[1][3]);
                    acc[2][0] = fmaf(av2, b4.x, acc[2][0]);
                    acc[2][1] = fmaf(av2, b4.y, acc[2][1]);
                    acc[2][2] = fmaf(av2, b4.z, acc[2][2]);
                    acc[2][3] = fmaf(av2, b4.w, acc[2][3]);
                    acc[3][0] = fmaf(av3, b4.x, acc[3][0]);
                    acc[3][1] = fmaf(av3, b4.y, acc[3][1]);
                    acc[3][2] = fmaf(av3, b4.z, acc[3][2]);
                    acc[3][3] = fmaf(av3, b4.w, acc[3][3]);
                }
            }

            const int wp = t & 1;
#pragma unroll
            for (int i = 0; i < 4; i++) {
                *(float4*)&g_partial[wp][ks][r0 + i][n0 + tx * 4] =
                    make_float4(acc[i][0], acc[i][1], acc[i][2], acc[i][3]);
            }

            // ---- full grid barrier (monotonic ticket; replay-safe) ----
            __threadfence();
            __syncthreads();
            if (tid == 0) {
                unsigned tk = atomicAdd(&g_count, 1u);
                unsigned target = ((tk >> 7) + 1u) << 7;     // 128 arrivals
                while ((int)(*(volatile unsigned*)&g_count)
                       - (int)target < 0) { }
                __threadfence();
            }
            __syncthreads();
        }
    }
    // t = 511: owner-reduce already wrote h_511 into out — nothing to flush.
}

// ---------------------------------------------------------------------------
// kernel_launch: 2 graph nodes total.
// ---------------------------------------------------------------------------
extern "C" void kernel_launch(void* const* d_in, const int* in_sizes, int n_in,
                              void* d_out, int out_size)
{
    (void)in_sizes; (void)n_in; (void)out_size;
    const float* x    = (const float*)d_in[0];
    const float* Wx   = (const float*)d_in[1];
    const float* Wh   = (const float*)d_in[2];
    const float* bias = (const float*)d_in[3];
    float* out = (float*)d_out;

    // 1) xp = x @ Wx + b  -> out
    dim3 gridA(HDIM / 64, (BATCH * TSTEPS) / 64);
    xp_kernel<<<gridA, 256>>>(x, Wx, bias, out);

    // 2) persistent recurrence (single launch, internal barriers)
    cudaFuncSetAttribute(rnn_persistent,
                         cudaFuncAttributeMaxDynamicSharedMemorySize,
                         (int)sizeof(SmemLayout));
    rnn_persistent<<<GRID, 256, sizeof(SmemLayout)>>>(out, Wh);
}

// round 14
// speedup vs baseline: 4.2632x; 1.1592x over previous
#include <cuda_runtime.h>
#include <math.h>

// Problem constants
#define BATCH 64
#define TSTEPS 512
#define DDIM 128
#define HDIM 1024
#define GRID 128          // 16 n-tiles x 8 k-splits
#define KCHUNK 128
#define NTILE 64

// Double-buffered split-K partials: 2*8*64*1024*4B = 4 MB (static)
__device__ float g_partial[2][8][BATCH][HDIM];
// Monotonic barrier tickets (never reset; wrap-safe compares)
__device__ unsigned g_count;        // full grid barrier (128 arrivals/phase)
__device__ unsigned g_gcount[8];    // per-ks-group barriers (16 arrivals/phase)

// ---------------------------------------------------------------------------
// tf32 helpers
// ---------------------------------------------------------------------------
__device__ __forceinline__ unsigned f2tf32(float x) {
    unsigned u;
    asm("cvt.rna.tf32.f32 %0, %1;" : "=r"(u) : "f"(x));
    return u;
}

__device__ __forceinline__ void mma_tf32(
    float c[4], unsigned a0, unsigned a1, unsigned a2, unsigned a3,
    unsigned b0, unsigned b1)
{
    asm volatile(
        "mma.sync.aligned.m16n8k8.row.col.f32.tf32.tf32.f32 "
        "{%0,%1,%2,%3}, {%4,%5,%6,%7}, {%8,%9}, {%0,%1,%2,%3};"
        : "+f"(c[0]), "+f"(c[1]), "+f"(c[2]), "+f"(c[3])
        : "r"(a0), "r"(a1), "r"(a2), "r"(a3), "r"(b0), "r"(b1));
}

// ---------------------------------------------------------------------------
// Kernel A: xp = x @ Wx + b  -> out[B,T,H]   (M=32768, K=128, N=1024)
// ---------------------------------------------------------------------------
__global__ __launch_bounds__(256) void xp_kernel(
    const float* __restrict__ x,
    const float* __restrict__ Wx,
    const float* __restrict__ bias,
    float* __restrict__ out)
{
    __shared__ float xs[64][33];
    __shared__ float ws[32][68];

    const int bx = blockIdx.x;
    const int by = blockIdx.y;
    const int tid = threadIdx.x;
    const int tx = tid & 15;
    const int ty = tid >> 4;
    const int row0 = by * 64;
    const int col0 = bx * 64;

    float acc[4][4];
#pragma unroll
    for (int i = 0; i < 4; i++)
#pragma unroll
        for (int j = 0; j < 4; j++) acc[i][j] = 0.0f;

    for (int k0 = 0; k0 < DDIM; k0 += 32) {
        for (int i = tid; i < 512; i += 256) {
            int m = i >> 3;
            int c = (i & 7) << 2;
            float4 v = *(const float4*)&x[(size_t)(row0 + m) * DDIM + k0 + c];
            xs[m][c + 0] = v.x; xs[m][c + 1] = v.y;
            xs[m][c + 2] = v.z; xs[m][c + 3] = v.w;
        }
        for (int i = tid; i < 512; i += 256) {
            int k = i >> 4;
            int c = (i & 15) << 2;
            *(float4*)&ws[k][c] =
                *(const float4*)&Wx[(size_t)(k0 + k) * HDIM + col0 + c];
        }
        __syncthreads();

#pragma unroll
        for (int kk = 0; kk < 32; kk++) {
            float a[4], bv[4];
#pragma unroll
            for (int i = 0; i < 4; i++) a[i] = xs[ty * 4 + i][kk];
#pragma unroll
            for (int j = 0; j < 4; j++) bv[j] = ws[kk][tx * 4 + j];
#pragma unroll
            for (int i = 0; i < 4; i++)
#pragma unroll
                for (int j = 0; j < 4; j++)
                    acc[i][j] = fmaf(a[i], bv[j], acc[i][j]);
        }
        __syncthreads();
    }

#pragma unroll
    for (int i = 0; i < 4; i++) {
        int row = row0 + ty * 4 + i;
#pragma unroll
        for (int j = 0; j < 4; j++) {
            int col = col0 + tx * 4 + j;
            out[(size_t)row * HDIM + col] = acc[i][j] + bias[col];
        }
    }
}

// ---------------------------------------------------------------------------
// Kernel B: persistent recurrence, tensor-core GEMM core.
// 128 blocks = (16 n-tiles nb) x (8 k-splits ks). Phase t for block (nb,ks):
//   owner-reduce rows nb*4..nb*4+3 of chunk ks -> tanh -> in place into out
//   group barrier (16 blocks sharing ks)
//   warp w loads h rows 8w..8w+7 -> smem; named barrier per warp pair
//   tf32 3-term mma GEMM: partial[wp][ks][:, nb-tile] = hs @ Wh_tile
//   full grid barrier
// Wh tile pre-split (tf32 hi/lo) + transposed into smem once.
// ---------------------------------------------------------------------------
struct SmemLayout {
    float hs[64][132];       // h_t chunk [m][k] fp32, padded
    float wshi[64][132];     // Wh tile transposed [n][k], tf32-hi bits
    float wslo[64][132];     // Wh tile transposed [n][k], tf32-lo bits
};

__global__ void __launch_bounds__(256, 1) rnn_persistent(
    float* __restrict__ out,
    const float* __restrict__ Wh)
{
    extern __shared__ char smem_raw[];
    SmemLayout* sm = reinterpret_cast<SmemLayout*>(smem_raw);

    const int bx = blockIdx.x;
    const int ks = bx >> 4;          // 0..7  k-split
    const int nb = bx & 15;          // 0..15 n-tile
    const int k0 = ks * KCHUNK;
    const int n0 = nb * NTILE;
    const int tid = threadIdx.x;
    const int w  = tid >> 5;         // warp 0..7
    const int ln = tid & 31;
    const int wm = w >> 1;           // m-tile 0..3 (rows wm*16..wm*16+15)
    const int wn = w & 1;            // n-half 0/1 (cols wn*32..wn*32+31)

    // ---- one-time: load Wh tile, split to tf32 hi/lo, store transposed ----
    for (int i = tid; i < KCHUNK * NTILE; i += 256) {
        int k = i >> 6;              // 0..127
        int n = i & 63;              // 0..63
        float v = Wh[(size_t)(k0 + k) * HDIM + n0 + n];
        unsigned hi = f2tf32(v);
        float lo_f = v - __uint_as_float(hi);
        sm->wshi[n][k] = __uint_as_float(hi);
        sm->wslo[n][k] = __uint_as_float(f2tf32(lo_f));
    }
    __syncthreads();

    // Owner-reduce mapping (threads 0..127): row nb*4 + (tid>>5), col4 = tid&31
    const int orow = nb * 4 + (tid >> 5);
    const int oc   = (tid & 31) << 2;

    // mma fragment lane mapping
    const int frow = ln >> 2;        // 0..7
    const int fcol = ln & 3;         // 0..3

    for (int t = 0; t < TSTEPS; t++) {
        // ---- owner-reduce: 4 rows of this k-chunk, written in place ----
        if (tid < 128) {
            float* xp_ptr = out + (size_t)orow * TSTEPS * HDIM
                            + (size_t)t * HDIM + k0 + oc;
            float4 s = *(const float4*)xp_ptr;
            if (t > 0) {
                const int rp = (t - 1) & 1;
#pragma unroll
                for (int sp = 0; sp < 8; sp++) {
                    float4 p = __ldcg((const float4*)
                        &g_partial[rp][sp][orow][k0 + oc]);
                    s.x += p.x; s.y += p.y; s.z += p.z; s.w += p.w;
                }
            }
            s.x = tanhf(s.x); s.y = tanhf(s.y);
            s.z = tanhf(s.z); s.w = tanhf(s.w);
            *(float4*)xp_ptr = s;     // out[:,t,:] now holds h_t (this slice)
        }

        if (t < TSTEPS - 1) {
            // ---- group barrier: 16 blocks sharing this ks ----
            __threadfence();
            __syncthreads();
            if (tid == 0) {
                unsigned tk = atomicAdd(&g_gcount[ks], 1u);
                unsigned target = ((tk >> 4) + 1u) << 4;     // 16 arrivals
                while ((int)(*(volatile unsigned*)&g_gcount[ks])
                       - (int)target < 0) { }
                __threadfence();
            }
            __syncthreads();

            // ---- warp w: load h rows 8w..8w+7 from out into smem ----
            {
                const size_t hb = (size_t)t * HDIM + k0;
#pragma unroll
                for (int j = ln; j < 256; j += 32) {
                    int m = (w << 3) + (j >> 5);
                    int c = (j & 31) << 2;
                    *(float4*)&sm->hs[m][c] = __ldcg((const float4*)
                        &out[(size_t)m * TSTEPS * HDIM + hb + c]);
                }
            }
            // warp pair (2*wm, 2*wm+1) shares rows wm*16..wm*16+15
            asm volatile("bar.sync %0, 64;" :: "r"(1 + wm) : "memory");

            // ---- tf32 mma GEMM: C[16x32] per warp ----
            float c[4][4];
#pragma unroll
            for (int j = 0; j < 4; j++)
#pragma unroll
                for (int i = 0; i < 4; i++) c[j][i] = 0.0f;

            const int ar = wm * 16 + frow;
            const int nbw = wn * 32;
#pragma unroll 4
            for (int kk = 0; kk < KCHUNK; kk += 8) {
                // A fragment (fp32 -> tf32 hi/lo split in registers)
                float a0f = sm->hs[ar    ][kk     + fcol];
                float a1f = sm->hs[ar + 8][kk     + fcol];
                float a2f = sm->hs[ar    ][kk + 4 + fcol];
                float a3f = sm->hs[ar + 8][kk + 4 + fcol];
                unsigned ah0 = f2tf32(a0f), ah1 = f2tf32(a1f);
                unsigned ah2 = f2tf32(a2f), ah3 = f2tf32(a3f);
                unsigned al0 = f2tf32(a0f - __uint_as_float(ah0));
                unsigned al1 = f2tf32(a1f - __uint_as_float(ah1));
                unsigned al2 = f2tf32(a2f - __uint_as_float(ah2));
                unsigned al3 = f2tf32(a3f - __uint_as_float(ah3));

#pragma unroll
                for (int j = 0; j < 4; j++) {
                    const int nn = nbw + j * 8 + frow;
                    unsigned bh0 = __float_as_uint(sm->wshi[nn][kk     + fcol]);
                    unsigned bh1 = __float_as_uint(sm->wshi[nn][kk + 4 + fcol]);
                    unsigned bl0 = __float_as_uint(sm->wslo[nn][kk     + fcol]);
                    unsigned bl1 = __float_as_uint(sm->wslo[nn][kk + 4 + fcol]);
                    mma_tf32(c[j], ah0, ah1, ah2, ah3, bh0, bh1);
                    mma_tf32(c[j], al0, al1, al2, al3, bh0, bh1);
                    mma_tf32(c[j], ah0, ah1, ah2, ah3, bl0, bl1);
                }
            }

            // ---- store partials ----
            const int wp = t & 1;
            {
                const int m0 = wm * 16 + frow;
#pragma unroll
                for (int j = 0; j < 4; j++) {
                    const int coln = n0 + nbw + j * 8 + fcol * 2;
                    *(float2*)&g_partial[wp][ks][m0    ][coln] =
                        make_float2(c[j][0], c[j][1]);
                    *(float2*)&g_partial[wp][ks][m0 + 8][coln] =
                        make_float2(c[j][2], c[j][3]);
                }
            }

            // ---- full grid barrier (monotonic ticket; replay-safe) ----
            __threadfence();
            __syncthreads();
            if (tid == 0) {
                unsigned tk = atomicAdd(&g_count, 1u);
                unsigned target = ((tk >> 7) + 1u) << 7;     // 128 arrivals
                while ((int)(*(volatile unsigned*)&g_count)
                       - (int)target < 0) { }
                __threadfence();
            }
            __syncthreads();
        }
    }
    // t = 511: owner-reduce already wrote h_511 into out — nothing to flush.
}

// ---------------------------------------------------------------------------
// kernel_launch: 2 graph nodes total.
// ---------------------------------------------------------------------------
extern "C" void kernel_launch(void* const* d_in, const int* in_sizes, int n_in,
                              void* d_out, int out_size)
{
    (void)in_sizes; (void)n_in; (void)out_size;
    const float* x    = (const float*)d_in[0];
    const float* Wx   = (const float*)d_in[1];
    const float* Wh   = (const float*)d_in[2];
    const float* bias = (const float*)d_in[3];
    float* out = (float*)d_out;

    // 1) xp = x @ Wx + b  -> out
    dim3 gridA(HDIM / 64, (BATCH * TSTEPS) / 64);
    xp_kernel<<<gridA, 256>>>(x, Wx, bias, out);

    // 2) persistent recurrence (single launch, internal barriers)
    cudaFuncSetAttribute(rnn_persistent,
                         cudaFuncAttributeMaxDynamicSharedMemorySize,
                         (int)sizeof(SmemLayout));
    rnn_persistent<<<GRID, 256, sizeof(SmemLayout)>>>(out, Wh);
}